// round 13
// baseline (speedup 1.0000x reference)
#include <cuda_runtime.h>
#include <cuda_bf16.h>
#include <cstdint>

#define NN   50000
#define NPAD 50048          // padded rows (multiple of 128)
#define NE   800000
#define D    128
#define NBLK 196            // ceil(50000/256)
#define STRD 136            // bf16 elems per row (272B, pad -> conflict-free LDSM)
#define TILE_B (128 * STRD * 2)       // 34816 bytes per tile
#define GB    391                     // ceil(50000/128)

// ---------------- scratch (device globals; no allocation allowed) ----------
__device__ float g_g0[NN * D];       // layer-0 g
__device__ float g_g1[NN * D];       // layer-1 g
__device__ float g_sv0[NN], g_dv0[NN];
__device__ float g_sv1[NN], g_dv1[NN];
__device__ int   g_deg[NN];          // zero at load; re-zeroed by k_scan_final
__device__ int   g_off[NN + 1];
__device__ int   g_cur[NN];
__device__ int   g_csr[NE + NN];
__device__ int   g_bsum[NBLK];
// encoder h carried pre-split (bf16 hi/lo, padded STRD layout, LDSM-ready).
__device__ __align__(16) __nv_bfloat16 g_ahi[NPAD * STRD];
__device__ __align__(16) __nv_bfloat16 g_alo[NPAD * STRD];

// ---------------- PTX helpers ----------------------------------------------
__device__ __forceinline__ uint32_t smem_u32(const void* p) {
    uint32_t a;
    asm("{ .reg .u64 t; cvta.to.shared.u64 t, %1; cvt.u32.u64 %0, t; }"
        : "=r"(a) : "l"(p));
    return a;
}
__device__ __forceinline__ void ldm_x4(uint32_t* r, uint32_t addr) {
    asm volatile("ldmatrix.sync.aligned.m8n8.x4.shared.b16 {%0,%1,%2,%3}, [%4];"
                 : "=r"(r[0]), "=r"(r[1]), "=r"(r[2]), "=r"(r[3]) : "r"(addr));
}
__device__ __forceinline__ void mma_bf16(float* d, const uint32_t* a,
                                         uint32_t b0, uint32_t b1) {
    asm volatile("mma.sync.aligned.m16n8k16.row.col.f32.bf16.bf16.f32 "
                 "{%0,%1,%2,%3}, {%4,%5,%6,%7}, {%8,%9}, {%0,%1,%2,%3};"
                 : "+f"(d[0]), "+f"(d[1]), "+f"(d[2]), "+f"(d[3])
                 : "r"(a[0]), "r"(a[1]), "r"(a[2]), "r"(a[3]), "r"(b0), "r"(b1));
}
__device__ __forceinline__ void split2(float a, float b,
                                       __nv_bfloat162& hi, __nv_bfloat162& lo) {
    __nv_bfloat16 h0 = __float2bfloat16(a), h1 = __float2bfloat16(b);
    hi.x = h0; hi.y = h1;
    lo.x = __float2bfloat16(a - __bfloat162float(h0));
    lo.y = __float2bfloat16(b - __bfloat162float(h1));
}

// warp-collective softmax-aggregate for one node v; returns out row (4 floats
// per lane = dims lane*4..lane*4+3), = sum_u alpha_u * G[u] + bias (b4).
__device__ __forceinline__ float4 agg_node(
    int v, const float4* __restrict__ G4,
    const float* __restrict__ sv, const float* __restrict__ dv,
    float4 b4, int lane)
{
    const int beg = g_off[v], end = g_off[v + 1];
    const float dvv = dv[v];
    float4 acc = make_float4(0.f, 0.f, 0.f, 0.f);
    float z = 0.f;
    for (int cs = beg; cs < end; cs += 32) {
        const int cnt = min(32, end - cs);
        int u = 0; float wv = 0.f;
        if (lane < cnt) {
            u = g_csr[cs + lane];
            float e = sv[u] + dvv;
            e = (e > 0.f) ? e : 0.2f * e;
            wv = __expf(e);
            z += wv;
        }
        int e = 0;
        for (; e + 4 <= cnt; e += 4) {
            float w0 = __shfl_sync(0xffffffffu, wv, e);
            float w1 = __shfl_sync(0xffffffffu, wv, e + 1);
            float w2 = __shfl_sync(0xffffffffu, wv, e + 2);
            float w3 = __shfl_sync(0xffffffffu, wv, e + 3);
            int   u0 = __shfl_sync(0xffffffffu, u, e);
            int   u1 = __shfl_sync(0xffffffffu, u, e + 1);
            int   u2 = __shfl_sync(0xffffffffu, u, e + 2);
            int   u3 = __shfl_sync(0xffffffffu, u, e + 3);
            float4 g0 = G4[u0 * 32 + lane];
            float4 g1 = G4[u1 * 32 + lane];
            float4 g2 = G4[u2 * 32 + lane];
            float4 g3 = G4[u3 * 32 + lane];
            acc.x = fmaf(w0, g0.x, acc.x); acc.y = fmaf(w0, g0.y, acc.y);
            acc.z = fmaf(w0, g0.z, acc.z); acc.w = fmaf(w0, g0.w, acc.w);
            acc.x = fmaf(w1, g1.x, acc.x); acc.y = fmaf(w1, g1.y, acc.y);
            acc.z = fmaf(w1, g1.z, acc.z); acc.w = fmaf(w1, g1.w, acc.w);
            acc.x = fmaf(w2, g2.x, acc.x); acc.y = fmaf(w2, g2.y, acc.y);
            acc.z = fmaf(w2, g2.z, acc.z); acc.w = fmaf(w2, g2.w, acc.w);
            acc.x = fmaf(w3, g3.x, acc.x); acc.y = fmaf(w3, g3.y, acc.y);
            acc.z = fmaf(w3, g3.z, acc.z); acc.w = fmaf(w3, g3.w, acc.w);
        }
        for (; e < cnt; e++) {
            float we = __shfl_sync(0xffffffffu, wv, e);
            int   ue = __shfl_sync(0xffffffffu, u, e);
            float4 gv = G4[ue * 32 + lane];
            acc.x = fmaf(we, gv.x, acc.x); acc.y = fmaf(we, gv.y, acc.y);
            acc.z = fmaf(we, gv.z, acc.z); acc.w = fmaf(we, gv.w, acc.w);
        }
    }
#pragma unroll
    for (int o = 16; o >= 1; o >>= 1) z += __shfl_xor_sync(0xffffffffu, z, o);
    const float inv = 1.f / z;
    float4 o4;
    o4.x = acc.x * inv + b4.x;
    o4.y = acc.y * inv + b4.y;
    o4.z = acc.z * inv + b4.z;
    o4.w = acc.w * inv + b4.w;
    return o4;
}

// ============ encoder GEMM: (x @ W + b) -> split hi/lo bf16 =================
__global__ __launch_bounds__(256, 1) void gemm_enc(
    const float* __restrict__ A, const float* __restrict__ Bw,
    const float* __restrict__ bias, int nrows)
{
    extern __shared__ __align__(16) char sm[];
    __shared__ float s_b[D];
    const int tid  = threadIdx.x, wid = tid >> 5, lane = tid & 31;
    const int row0 = blockIdx.x * 128;
    const uint32_t smb = smem_u32(sm);
    const int A_HI = 0, A_LO = TILE_B, B_HI = 2 * TILE_B, B_LO = 3 * TILE_B;

    if (tid < 128) s_b[tid] = bias[tid];

    const float2* A2 = (const float2*)A;
#pragma unroll
    for (int i = 0; i < 32; i++) {
        int idx = tid + i * 256;
        int row = idx >> 6;
        int kp  = idx & 63;
        float2 v = make_float2(0.f, 0.f);
        int gr = row0 + row;
        if (gr < nrows) v = A2[gr * 64 + kp];
        __nv_bfloat162 Hi, Lo;
        split2(v.x, v.y, Hi, Lo);
        int off = row * STRD + 2 * kp;
        *(__nv_bfloat162*)(sm + A_HI + off * 2) = Hi;
        *(__nv_bfloat162*)(sm + A_LO + off * 2) = Lo;
    }
#pragma unroll
    for (int i = 0; i < 32; i++) {
        int idx = tid + i * 256;
        int n   = idx & 127;
        int kp  = idx >> 7;
        float b0 = Bw[(2 * kp) * 128 + n];
        float b1 = Bw[(2 * kp + 1) * 128 + n];
        __nv_bfloat162 Hi, Lo;
        split2(b0, b1, Hi, Lo);
        int off = n * STRD + 2 * kp;
        *(__nv_bfloat162*)(sm + B_HI + off * 2) = Hi;
        *(__nv_bfloat162*)(sm + B_LO + off * 2) = Lo;
    }
    __syncthreads();

    const int warpM = wid >> 1, warpN = wid & 1;
    const int lr = lane & 15, lc = (lane >> 4) * 8;

    float acc[2][8][4];
#pragma unroll
    for (int mi = 0; mi < 2; mi++)
#pragma unroll
        for (int ni = 0; ni < 8; ni++)
#pragma unroll
            for (int c = 0; c < 4; c++) acc[mi][ni][c] = 0.f;

#pragma unroll
    for (int term = 0; term < 3; term++) {
        const int abase = (term == 1) ? A_LO : A_HI;
        const int bbase = (term == 2) ? B_LO : B_HI;
#pragma unroll
        for (int k0 = 0; k0 < 128; k0 += 16) {
            uint32_t af[2][4];
#pragma unroll
            for (int mi = 0; mi < 2; mi++)
                ldm_x4(af[mi], smb + abase +
                       ((warpM * 32 + mi * 16 + lr) * STRD + k0 + lc) * 2);
            uint32_t bf[4][4];
#pragma unroll
            for (int q = 0; q < 4; q++)
                ldm_x4(bf[q], smb + bbase +
                       ((warpN * 64 + q * 16 + lr) * STRD + k0 + lc) * 2);
#pragma unroll
            for (int mi = 0; mi < 2; mi++)
#pragma unroll
                for (int q = 0; q < 4; q++) {
                    mma_bf16(acc[mi][2 * q],     af[mi], bf[q][0], bf[q][2]);
                    mma_bf16(acc[mi][2 * q + 1], af[mi], bf[q][1], bf[q][3]);
                }
        }
    }

    const int g = lane >> 2, t4 = lane & 3;
#pragma unroll
    for (int mi = 0; mi < 2; mi++) {
        const int gr0 = row0 + warpM * 32 + mi * 16 + g;
        const int gr1 = gr0 + 8;
#pragma unroll
        for (int ni = 0; ni < 8; ni++) {
            const int col = warpN * 64 + ni * 8 + 2 * t4;
            if (gr0 < nrows) {
                __nv_bfloat162 Hi, Lo;
                split2(acc[mi][ni][0] + s_b[col], acc[mi][ni][1] + s_b[col + 1], Hi, Lo);
                *(__nv_bfloat162*)((char*)g_ahi + gr0 * (STRD * 2) + col * 2) = Hi;
                *(__nv_bfloat162*)((char*)g_alo + gr0 * (STRD * 2) + col * 2) = Lo;
            }
            if (gr1 < nrows) {
                __nv_bfloat162 Hi, Lo;
                split2(acc[mi][ni][2] + s_b[col], acc[mi][ni][3] + s_b[col + 1], Hi, Lo);
                *(__nv_bfloat162*)((char*)g_ahi + gr1 * (STRD * 2) + col * 2) = Hi;
                *(__nv_bfloat162*)((char*)g_alo + gr1 * (STRD * 2) + col * 2) = Lo;
            }
        }
    }
}

// ======== layer GEMM (layer 0): g = h @ W; sv/dv epilogue dots ==============
// A comes pre-split from g_ahi/g_alo (raw 16B copies).
__global__ __launch_bounds__(256, 1) void gemm_lyr(
    const float* __restrict__ Bw,
    const float* __restrict__ asrc, const float* __restrict__ adst,
    float* __restrict__ C, float* __restrict__ svO, float* __restrict__ dvO,
    int nrows)
{
    extern __shared__ __align__(16) char sm[];
    __shared__ float s_as[D], s_ad[D], s_s[D], s_d[D];
    const int tid  = threadIdx.x, wid = tid >> 5, lane = tid & 31;
    const int row0 = blockIdx.x * 128;
    const uint32_t smb = smem_u32(sm);
    const int A_HI = 0, A_LO = TILE_B, B_HI = 2 * TILE_B, B_LO = 3 * TILE_B;

    if (tid < 128) {
        s_as[tid] = asrc[tid];
        s_ad[tid] = adst[tid];
        s_s[tid] = 0.f;
        s_d[tid] = 0.f;
    }
    {
        const uint4* __restrict__ shi = (const uint4*)g_ahi + (size_t)row0 * 17;
        const uint4* __restrict__ slo = (const uint4*)g_alo + (size_t)row0 * 17;
        uint4* dhi = (uint4*)(sm + A_HI);
        uint4* dlo = (uint4*)(sm + A_LO);
#pragma unroll
        for (int i = 0; i < 9; i++) {
            int idx = tid + i * 256;
            if (idx < 128 * 17) { dhi[idx] = shi[idx]; dlo[idx] = slo[idx]; }
        }
    }
#pragma unroll
    for (int i = 0; i < 32; i++) {
        int idx = tid + i * 256;
        int n   = idx & 127;
        int kp  = idx >> 7;
        float b0 = Bw[(2 * kp) * 128 + n];
        float b1 = Bw[(2 * kp + 1) * 128 + n];
        __nv_bfloat162 Hi, Lo;
        split2(b0, b1, Hi, Lo);
        int off = n * STRD + 2 * kp;
        *(__nv_bfloat162*)(sm + B_HI + off * 2) = Hi;
        *(__nv_bfloat162*)(sm + B_LO + off * 2) = Lo;
    }
    __syncthreads();

    const int warpM = wid >> 1, warpN = wid & 1;
    const int lr = lane & 15, lc = (lane >> 4) * 8;

    float acc[2][8][4];
#pragma unroll
    for (int mi = 0; mi < 2; mi++)
#pragma unroll
        for (int ni = 0; ni < 8; ni++)
#pragma unroll
            for (int c = 0; c < 4; c++) acc[mi][ni][c] = 0.f;

#pragma unroll
    for (int term = 0; term < 3; term++) {
        const int abase = (term == 1) ? A_LO : A_HI;
        const int bbase = (term == 2) ? B_LO : B_HI;
#pragma unroll
        for (int k0 = 0; k0 < 128; k0 += 16) {
            uint32_t af[2][4];
#pragma unroll
            for (int mi = 0; mi < 2; mi++)
                ldm_x4(af[mi], smb + abase +
                       ((warpM * 32 + mi * 16 + lr) * STRD + k0 + lc) * 2);
            uint32_t bf[4][4];
#pragma unroll
            for (int q = 0; q < 4; q++)
                ldm_x4(bf[q], smb + bbase +
                       ((warpN * 64 + q * 16 + lr) * STRD + k0 + lc) * 2);
#pragma unroll
            for (int mi = 0; mi < 2; mi++)
#pragma unroll
                for (int q = 0; q < 4; q++) {
                    mma_bf16(acc[mi][2 * q],     af[mi], bf[q][0], bf[q][2]);
                    mma_bf16(acc[mi][2 * q + 1], af[mi], bf[q][1], bf[q][3]);
                }
        }
    }

    const int g = lane >> 2, t4 = lane & 3;
    float sp[2][2], dp[2][2];
#pragma unroll
    for (int mi = 0; mi < 2; mi++) { sp[mi][0] = sp[mi][1] = 0.f; dp[mi][0] = dp[mi][1] = 0.f; }

    float2* C2 = (float2*)C;
#pragma unroll
    for (int mi = 0; mi < 2; mi++) {
        const int gr0 = row0 + warpM * 32 + mi * 16 + g;
        const int gr1 = gr0 + 8;
#pragma unroll
        for (int ni = 0; ni < 8; ni++) {
            const int col = warpN * 64 + ni * 8 + 2 * t4;
            float c0 = acc[mi][ni][0], c1 = acc[mi][ni][1];
            float c2 = acc[mi][ni][2], c3 = acc[mi][ni][3];
            sp[mi][0] = fmaf(c0, s_as[col], fmaf(c1, s_as[col + 1], sp[mi][0]));
            dp[mi][0] = fmaf(c0, s_ad[col], fmaf(c1, s_ad[col + 1], dp[mi][0]));
            sp[mi][1] = fmaf(c2, s_as[col], fmaf(c3, s_as[col + 1], sp[mi][1]));
            dp[mi][1] = fmaf(c2, s_ad[col], fmaf(c3, s_ad[col + 1], dp[mi][1]));
            if (gr0 < nrows) {
                float2 o; o.x = c0; o.y = c1;
                C2[gr0 * 64 + (col >> 1)] = o;
            }
            if (gr1 < nrows) {
                float2 o; o.x = c2; o.y = c3;
                C2[gr1 * 64 + (col >> 1)] = o;
            }
        }
    }
#pragma unroll
    for (int mi = 0; mi < 2; mi++)
#pragma unroll
        for (int hh = 0; hh < 2; hh++) {
#pragma unroll
            for (int o = 1; o <= 2; o <<= 1) {
                sp[mi][hh] += __shfl_xor_sync(0xffffffffu, sp[mi][hh], o);
                dp[mi][hh] += __shfl_xor_sync(0xffffffffu, dp[mi][hh], o);
            }
            if (t4 == 0) {
                int rl = warpM * 32 + mi * 16 + g + hh * 8;
                atomicAdd(&s_s[rl], sp[mi][hh]);
                atomicAdd(&s_d[rl], dp[mi][hh]);
            }
        }
    __syncthreads();
    if (tid < 128 && row0 + tid < nrows) {
        svO[row0 + tid] = s_s[tid];
        dvO[row0 + tid] = s_d[tid];
    }
}

// ======== FUSED: agg(layer0) for own 128 rows -> smem -> GEMM(layer1) =======
// Deletes the standalone agg0 launch and the global h round-trip.
__global__ __launch_bounds__(256, 1) void fused_agg_gemm(
    const float* __restrict__ bias0,            // layer-0 bias (agg epilogue)
    const float* __restrict__ Bw,               // W1
    const float* __restrict__ asrc, const float* __restrict__ adst,
    float* __restrict__ C, float* __restrict__ svO, float* __restrict__ dvO,
    const float* __restrict__ G, const float* __restrict__ sv,
    const float* __restrict__ dv, int nrows)
{
    extern __shared__ __align__(16) char sm[];
    __shared__ float s_as[D], s_ad[D], s_s[D], s_d[D];
    const int tid  = threadIdx.x, wid = tid >> 5, lane = tid & 31;
    const int row0 = blockIdx.x * 128;
    const uint32_t smb = smem_u32(sm);
    const int A_HI = 0, A_LO = TILE_B, B_HI = 2 * TILE_B, B_LO = 3 * TILE_B;

    if (tid < 128) {
        s_as[tid] = asrc[tid];
        s_ad[tid] = adst[tid];
        s_s[tid] = 0.f;
        s_d[tid] = 0.f;
    }
    // ---- B: W1 split (global reads issued first; independent of agg) ----
#pragma unroll
    for (int i = 0; i < 32; i++) {
        int idx = tid + i * 256;
        int n   = idx & 127;
        int kp  = idx >> 7;
        float b0 = Bw[(2 * kp) * 128 + n];
        float b1 = Bw[(2 * kp + 1) * 128 + n];
        __nv_bfloat162 Hi, Lo;
        split2(b0, b1, Hi, Lo);
        int off = n * STRD + 2 * kp;
        *(__nv_bfloat162*)(sm + B_HI + off * 2) = Hi;
        *(__nv_bfloat162*)(sm + B_LO + off * 2) = Lo;
    }

    // ---- phase 1: agg layer 0 for this tile's 128 rows -> smem A tiles ----
    {
        const float4* __restrict__ G4 = (const float4*)G;
        const float4 b4 = ((const float4*)bias0)[lane];
#pragma unroll 1
        for (int j = 0; j < 16; j++) {
            const int r = wid * 16 + j;              // local row 0..127
            const int v = row0 + r;
            float4 o4 = make_float4(0.f, 0.f, 0.f, 0.f);
            if (v < nrows) o4 = agg_node(v, G4, sv, dv, b4, lane);
            __nv_bfloat162 h0, l0, h1, l1;
            split2(o4.x, o4.y, h0, l0);
            split2(o4.z, o4.w, h1, l1);
            const int off = (r * STRD + lane * 4) * 2;   // bytes
            *(__nv_bfloat162*)(sm + A_HI + off)     = h0;
            *(__nv_bfloat162*)(sm + A_HI + off + 4) = h1;
            *(__nv_bfloat162*)(sm + A_LO + off)     = l0;
            *(__nv_bfloat162*)(sm + A_LO + off + 4) = l1;
        }
    }
    __syncthreads();

    // ---- phase 2: GEMM h @ W1 (identical to gemm_lyr mainloop) ----
    const int warpM = wid >> 1, warpN = wid & 1;
    const int lr = lane & 15, lc = (lane >> 4) * 8;

    float acc[2][8][4];
#pragma unroll
    for (int mi = 0; mi < 2; mi++)
#pragma unroll
        for (int ni = 0; ni < 8; ni++)
#pragma unroll
            for (int c = 0; c < 4; c++) acc[mi][ni][c] = 0.f;

#pragma unroll
    for (int term = 0; term < 3; term++) {
        const int abase = (term == 1) ? A_LO : A_HI;
        const int bbase = (term == 2) ? B_LO : B_HI;
#pragma unroll
        for (int k0 = 0; k0 < 128; k0 += 16) {
            uint32_t af[2][4];
#pragma unroll
            for (int mi = 0; mi < 2; mi++)
                ldm_x4(af[mi], smb + abase +
                       ((warpM * 32 + mi * 16 + lr) * STRD + k0 + lc) * 2);
            uint32_t bf[4][4];
#pragma unroll
            for (int q = 0; q < 4; q++)
                ldm_x4(bf[q], smb + bbase +
                       ((warpN * 64 + q * 16 + lr) * STRD + k0 + lc) * 2);
#pragma unroll
            for (int mi = 0; mi < 2; mi++)
#pragma unroll
                for (int q = 0; q < 4; q++) {
                    mma_bf16(acc[mi][2 * q],     af[mi], bf[q][0], bf[q][2]);
                    mma_bf16(acc[mi][2 * q + 1], af[mi], bf[q][1], bf[q][3]);
                }
        }
    }

    const int g = lane >> 2, t4 = lane & 3;
    float sp[2][2], dp[2][2];
#pragma unroll
    for (int mi = 0; mi < 2; mi++) { sp[mi][0] = sp[mi][1] = 0.f; dp[mi][0] = dp[mi][1] = 0.f; }

    float2* C2 = (float2*)C;
#pragma unroll
    for (int mi = 0; mi < 2; mi++) {
        const int gr0 = row0 + warpM * 32 + mi * 16 + g;
        const int gr1 = gr0 + 8;
#pragma unroll
        for (int ni = 0; ni < 8; ni++) {
            const int col = warpN * 64 + ni * 8 + 2 * t4;
            float c0 = acc[mi][ni][0], c1 = acc[mi][ni][1];
            float c2 = acc[mi][ni][2], c3 = acc[mi][ni][3];
            sp[mi][0] = fmaf(c0, s_as[col], fmaf(c1, s_as[col + 1], sp[mi][0]));
            dp[mi][0] = fmaf(c0, s_ad[col], fmaf(c1, s_ad[col + 1], dp[mi][0]));
            sp[mi][1] = fmaf(c2, s_as[col], fmaf(c3, s_as[col + 1], sp[mi][1]));
            dp[mi][1] = fmaf(c2, s_ad[col], fmaf(c3, s_ad[col + 1], dp[mi][1]));
            if (gr0 < nrows) {
                float2 o; o.x = c0; o.y = c1;
                C2[gr0 * 64 + (col >> 1)] = o;
            }
            if (gr1 < nrows) {
                float2 o; o.x = c2; o.y = c3;
                C2[gr1 * 64 + (col >> 1)] = o;
            }
        }
    }
#pragma unroll
    for (int mi = 0; mi < 2; mi++)
#pragma unroll
        for (int hh = 0; hh < 2; hh++) {
#pragma unroll
            for (int o = 1; o <= 2; o <<= 1) {
                sp[mi][hh] += __shfl_xor_sync(0xffffffffu, sp[mi][hh], o);
                dp[mi][hh] += __shfl_xor_sync(0xffffffffu, dp[mi][hh], o);
            }
            if (t4 == 0) {
                int rl = warpM * 32 + mi * 16 + g + hh * 8;
                atomicAdd(&s_s[rl], sp[mi][hh]);
                atomicAdd(&s_d[rl], dp[mi][hh]);
            }
        }
    __syncthreads();
    if (tid < 128 && row0 + tid < nrows) {
        svO[row0 + tid] = s_s[tid];
        dvO[row0 + tid] = s_d[tid];
    }
}

// ---------------- CSR build (group edges by destination) -------------------
__global__ void k_deg_count(const int* __restrict__ dst) {
    int i = blockIdx.x * blockDim.x + threadIdx.x;
    if (i < NE) atomicAdd(&g_deg[dst[i]], 1);
}
__global__ void k_block_sums() {
    __shared__ int red[8];
    int b = blockIdx.x, t = threadIdx.x;
    int i = b * 256 + t;
    int v = (i < NN) ? (g_deg[i] + 1) : 0;           // +1 = self-loop
#pragma unroll
    for (int o = 16; o >= 1; o >>= 1) v += __shfl_xor_sync(0xffffffffu, v, o);
    if ((t & 31) == 0) red[t >> 5] = v;
    __syncthreads();
    if (t == 0) {
        int s = 0;
        for (int w = 0; w < 8; w++) s += red[w];
        g_bsum[b] = s;
    }
}
__global__ void k_scan_bsums() {
    __shared__ int sh[256];
    int t = threadIdx.x;
    int v = (t < NBLK) ? g_bsum[t] : 0;
    sh[t] = v;
    __syncthreads();
    for (int o = 1; o < 256; o <<= 1) {
        int x = (t >= o) ? sh[t - o] : 0;
        __syncthreads();
        sh[t] += x;
        __syncthreads();
    }
    if (t < NBLK) g_bsum[t] = sh[t] - v;
    if (t == 255) g_off[NN] = sh[255];
}
__global__ void k_scan_final() {
    __shared__ int sh[256];
    int b = blockIdx.x, t = threadIdx.x;
    int i = b * 256 + t;
    int v = (i < NN) ? (g_deg[i] + 1) : 0;
    sh[t] = v;
    __syncthreads();
    for (int o = 1; o < 256; o <<= 1) {
        int x = (t >= o) ? sh[t - o] : 0;
        __syncthreads();
        sh[t] += x;
        __syncthreads();
    }
    if (i < NN) {
        int p = g_bsum[b] + sh[t] - v;
        g_off[i] = p;
        g_cur[i] = p;
        g_deg[i] = 0;
    }
}
__global__ void k_scatter(const int* __restrict__ src, const int* __restrict__ dst) {
    int i = blockIdx.x * blockDim.x + threadIdx.x;
    if (i < NE) {
        int p = atomicAdd(&g_cur[dst[i]], 1);
        g_csr[p] = src[i];
    } else if (i < NE + NN) {
        int n = i - NE;
        int p = atomicAdd(&g_cur[n], 1);
        g_csr[p] = n;
    }
}

// ---------------- final agg (layer 1) -> fp32 output -----------------------
#define AGG_WPB 8
__global__ __launch_bounds__(256) void agg_final(const float* __restrict__ bias,
                                                 float* __restrict__ outf,
                                                 const float* __restrict__ G,
                                                 const float* __restrict__ sv,
                                                 const float* __restrict__ dv)
{
    const int wid = threadIdx.x >> 5, lane = threadIdx.x & 31;
    const int v = blockIdx.x * AGG_WPB + wid;
    if (v >= NN) return;
    const float4 b4 = ((const float4*)bias)[lane];
    float4 o4 = agg_node(v, (const float4*)G, sv, dv, b4, lane);
    ((float4*)outf)[v * 32 + lane] = o4;
}

// ---------------- launch ---------------------------------------------------
extern "C" void kernel_launch(void* const* d_in, const int* in_sizes, int n_in,
                              void* d_out, int out_size)
{
    (void)in_sizes; (void)n_in; (void)out_size;
    const float* x      = (const float*)d_in[0];
    const int*   ei     = (const int*)  d_in[1];
    const float* W_node = (const float*)d_in[3];
    const float* b_node = (const float*)d_in[4];
    // d_in[2,5,6,7,8] (edge_attr / W_edge / b_edge / lyr_We / lyr_be) are dead
    // code in the reference: their results are discarded before the output.
    const float* lyr_W  = (const float*)d_in[9];
    const float* att_s  = (const float*)d_in[10];
    const float* att_d  = (const float*)d_in[11];
    const float* lyr_b  = (const float*)d_in[12];
    float* out = (float*)d_out;

    float *pG0, *pG1, *pSv0, *pDv0, *pSv1, *pDv1;
    cudaGetSymbolAddress((void**)&pG0, g_g0);
    cudaGetSymbolAddress((void**)&pG1, g_g1);
    cudaGetSymbolAddress((void**)&pSv0, g_sv0);
    cudaGetSymbolAddress((void**)&pDv0, g_dv0);
    cudaGetSymbolAddress((void**)&pSv1, g_sv1);
    cudaGetSymbolAddress((void**)&pDv1, g_dv1);

    const int SMEMSZ = 4 * TILE_B;                       // 139264 B
    cudaFuncSetAttribute(gemm_enc,
                         cudaFuncAttributeMaxDynamicSharedMemorySize, SMEMSZ);
    cudaFuncSetAttribute(gemm_lyr,
                         cudaFuncAttributeMaxDynamicSharedMemorySize, SMEMSZ);
    cudaFuncSetAttribute(fused_agg_gemm,
                         cudaFuncAttributeMaxDynamicSharedMemorySize, SMEMSZ);

    const int* src = ei;
    const int* dst = ei + NE;
    const int AGG_F = (NN + AGG_WPB - 1) / AGG_WPB;

    // One extra stream (round-11 lesson: >1 leaks launch pools past teardown).
    cudaStream_t s2;
    cudaStreamCreateWithFlags(&s2, cudaStreamNonBlocking);
    cudaEvent_t evFork, evCsr;
    cudaEventCreateWithFlags(&evFork, cudaEventDisableTiming);
    cudaEventCreateWithFlags(&evCsr, cudaEventDisableTiming);

    cudaEventRecord(evFork, (cudaStream_t)0);
    cudaStreamWaitEvent(s2, evFork, 0);

    // stream0: node encoder h = split(x @ W_node + b_node)
    gemm_enc<<<GB, 256, SMEMSZ>>>(x, W_node, b_node, NN);

    // s2: CSR build overlaps encoder + layer-0 GEMM.
    k_deg_count<<<(NE + 255) / 256, 256, 0, s2>>>(dst);
    k_block_sums<<<NBLK, 256, 0, s2>>>();
    k_scan_bsums<<<1, 256, 0, s2>>>();
    k_scan_final<<<NBLK, 256, 0, s2>>>();
    k_scatter<<<(NE + NN + 255) / 256, 256, 0, s2>>>(src, dst);
    cudaEventRecord(evCsr, s2);

    // stream0: layer-0 GEMM (needs enc only)
    gemm_lyr<<<GB, 256, SMEMSZ>>>(lyr_W, att_s, att_d, pG0, pSv0, pDv0, NN);

    // join CSR; fused agg(layer0)+GEMM(layer1); final agg -> out.
    cudaStreamWaitEvent((cudaStream_t)0, evCsr, 0);
    fused_agg_gemm<<<GB, 256, SMEMSZ>>>(lyr_b, lyr_W + D * D,
                                        att_s + D, att_d + D,
                                        pG1, pSv1, pDv1,
                                        pG0, pSv0, pDv0, NN);
    agg_final<<<AGG_F, 256>>>(lyr_b + D, out, pG1, pSv1, pDv1);
}

// round 14
// speedup vs baseline: 1.5352x; 1.5352x over previous
#include <cuda_runtime.h>
#include <cuda_bf16.h>
#include <cstdint>

#define NN   50000
#define NPAD 50048          // padded rows (multiple of 128)
#define NE   800000
#define D    128
#define NBLK 196            // ceil(50000/256)
#define STRD 136            // bf16 elems per row (272B, pad -> conflict-free LDSM)
#define TILE_B (128 * STRD * 2)       // 34816 bytes per tile
#define GB    391                     // ceil(50000/128)

// ---------------- scratch (device globals; no allocation allowed) ----------
__device__ float g_g[NN * D];
__device__ float g_sv[NN];
__device__ float g_dv[NN];
__device__ int   g_deg[NN];          // zero at load; re-zeroed by k_scan_final
__device__ int   g_off[NN + 1];
__device__ int   g_cur[NN];
__device__ int   g_csr[NE + NN];
__device__ int   g_bsum[NBLK];
// layer-1 input h carried pre-split (bf16 hi/lo, padded STRD layout).
__device__ __align__(16) __nv_bfloat16 g_ahi[NPAD * STRD];
__device__ __align__(16) __nv_bfloat16 g_alo[NPAD * STRD];

// ---------------- PTX helpers ----------------------------------------------
__device__ __forceinline__ uint32_t smem_u32(const void* p) {
    uint32_t a;
    asm("{ .reg .u64 t; cvta.to.shared.u64 t, %1; cvt.u32.u64 %0, t; }"
        : "=r"(a) : "l"(p));
    return a;
}
__device__ __forceinline__ void ldm_x4(uint32_t* r, uint32_t addr) {
    asm volatile("ldmatrix.sync.aligned.m8n8.x4.shared.b16 {%0,%1,%2,%3}, [%4];"
                 : "=r"(r[0]), "=r"(r[1]), "=r"(r[2]), "=r"(r[3]) : "r"(addr));
}
__device__ __forceinline__ void mma_bf16(float* d, const uint32_t* a,
                                         uint32_t b0, uint32_t b1) {
    asm volatile("mma.sync.aligned.m16n8k16.row.col.f32.bf16.bf16.f32 "
                 "{%0,%1,%2,%3}, {%4,%5,%6,%7}, {%8,%9}, {%0,%1,%2,%3};"
                 : "+f"(d[0]), "+f"(d[1]), "+f"(d[2]), "+f"(d[3])
                 : "r"(a[0]), "r"(a[1]), "r"(a[2]), "r"(a[3]), "r"(b0), "r"(b1));
}
__device__ __forceinline__ void split2(float a, float b,
                                       __nv_bfloat162& hi, __nv_bfloat162& lo) {
    __nv_bfloat16 h0 = __float2bfloat16(a), h1 = __float2bfloat16(b);
    hi.x = h0; hi.y = h1;
    lo.x = __float2bfloat16(a - __bfloat162float(h0));
    lo.y = __float2bfloat16(b - __bfloat162float(h1));
}

// ===== FUSED encoder + layer-0 GEMM =========================================
// Phase 1: h_tile = x_tile @ W0 + b0  (3-term bf16-split HMMA, acc fp32)
//          h never leaves the CTA: split straight into the smem A tile.
// Phase 2: g0_tile = h_tile @ W1; epilogue writes g0 + sv/dv dots.
__global__ __launch_bounds__(256, 1) void gemm_enc_lyr0(
    const float* __restrict__ A, const float* __restrict__ B0,
    const float* __restrict__ bias0,
    const float* __restrict__ B1,
    const float* __restrict__ asrc, const float* __restrict__ adst,
    float* __restrict__ C, int nrows)
{
    extern __shared__ __align__(16) char sm[];
    __shared__ float s_b[D], s_as[D], s_ad[D], s_s[D], s_d[D];
    const int tid  = threadIdx.x, wid = tid >> 5, lane = tid & 31;
    const int row0 = blockIdx.x * 128;
    const uint32_t smb = smem_u32(sm);
    const int A_HI = 0, A_LO = TILE_B, B_HI = 2 * TILE_B, B_LO = 3 * TILE_B;

    if (tid < 128) {
        s_b[tid]  = bias0[tid];
        s_as[tid] = asrc[tid];
        s_ad[tid] = adst[tid];
        s_s[tid]  = 0.f;
        s_d[tid]  = 0.f;
    }

    // ---- phase-1 A: x fp32 -> (hi, lo) bf16 tiles [row][k] ----
    const float2* A2 = (const float2*)A;
#pragma unroll
    for (int i = 0; i < 32; i++) {
        int idx = tid + i * 256;
        int row = idx >> 6;
        int kp  = idx & 63;
        float2 v = make_float2(0.f, 0.f);
        int gr = row0 + row;
        if (gr < nrows) v = A2[gr * 64 + kp];
        __nv_bfloat162 Hi, Lo;
        split2(v.x, v.y, Hi, Lo);
        int off = row * STRD + 2 * kp;
        *(__nv_bfloat162*)(sm + A_HI + off * 2) = Hi;
        *(__nv_bfloat162*)(sm + A_LO + off * 2) = Lo;
    }
    // ---- phase-1 B: W0[k][n] -> Bs[n][k] transposed, hi/lo split ----
#pragma unroll
    for (int i = 0; i < 32; i++) {
        int idx = tid + i * 256;
        int n   = idx & 127;
        int kp  = idx >> 7;
        float b0 = B0[(2 * kp) * 128 + n];
        float b1 = B0[(2 * kp + 1) * 128 + n];
        __nv_bfloat162 Hi, Lo;
        split2(b0, b1, Hi, Lo);
        int off = n * STRD + 2 * kp;
        *(__nv_bfloat162*)(sm + B_HI + off * 2) = Hi;
        *(__nv_bfloat162*)(sm + B_LO + off * 2) = Lo;
    }
    __syncthreads();

    const int warpM = wid >> 1, warpN = wid & 1;
    const int lr = lane & 15, lc = (lane >> 4) * 8;
    const int g = lane >> 2, t4 = lane & 3;

    float acc[2][8][4];
#pragma unroll
    for (int mi = 0; mi < 2; mi++)
#pragma unroll
        for (int ni = 0; ni < 8; ni++)
#pragma unroll
            for (int c = 0; c < 4; c++) acc[mi][ni][c] = 0.f;

    // ---- phase-1 mainloop: x @ W0 ----
#pragma unroll
    for (int term = 0; term < 3; term++) {
        const int abase = (term == 1) ? A_LO : A_HI;
        const int bbase = (term == 2) ? B_LO : B_HI;
#pragma unroll
        for (int k0 = 0; k0 < 128; k0 += 16) {
            uint32_t af[2][4];
#pragma unroll
            for (int mi = 0; mi < 2; mi++)
                ldm_x4(af[mi], smb + abase +
                       ((warpM * 32 + mi * 16 + lr) * STRD + k0 + lc) * 2);
            uint32_t bf[4][4];
#pragma unroll
            for (int q = 0; q < 4; q++)
                ldm_x4(bf[q], smb + bbase +
                       ((warpN * 64 + q * 16 + lr) * STRD + k0 + lc) * 2);
#pragma unroll
            for (int mi = 0; mi < 2; mi++)
#pragma unroll
                for (int q = 0; q < 4; q++) {
                    mma_bf16(acc[mi][2 * q],     af[mi], bf[q][0], bf[q][2]);
                    mma_bf16(acc[mi][2 * q + 1], af[mi], bf[q][1], bf[q][3]);
                }
        }
    }
    __syncthreads();   // all phase-1 LDSM done -> safe to overwrite A and B

    // ---- h = acc + bias0, split DIRECTLY into smem A tiles ----
#pragma unroll
    for (int mi = 0; mi < 2; mi++) {
        const int r0l = warpM * 32 + mi * 16 + g;    // local rows
        const int r1l = r0l + 8;
#pragma unroll
        for (int ni = 0; ni < 8; ni++) {
            const int col = warpN * 64 + ni * 8 + 2 * t4;
            __nv_bfloat162 Hi, Lo;
            split2(acc[mi][ni][0] + s_b[col], acc[mi][ni][1] + s_b[col + 1], Hi, Lo);
            int off0 = (r0l * STRD + col) * 2;
            *(__nv_bfloat162*)(sm + A_HI + off0) = Hi;
            *(__nv_bfloat162*)(sm + A_LO + off0) = Lo;
            split2(acc[mi][ni][2] + s_b[col], acc[mi][ni][3] + s_b[col + 1], Hi, Lo);
            int off1 = (r1l * STRD + col) * 2;
            *(__nv_bfloat162*)(sm + A_HI + off1) = Hi;
            *(__nv_bfloat162*)(sm + A_LO + off1) = Lo;
        }
    }
    // ---- phase-2 B: W1 split ----
#pragma unroll
    for (int i = 0; i < 32; i++) {
        int idx = tid + i * 256;
        int n   = idx & 127;
        int kp  = idx >> 7;
        float b0 = B1[(2 * kp) * 128 + n];
        float b1 = B1[(2 * kp + 1) * 128 + n];
        __nv_bfloat162 Hi, Lo;
        split2(b0, b1, Hi, Lo);
        int off = n * STRD + 2 * kp;
        *(__nv_bfloat162*)(sm + B_HI + off * 2) = Hi;
        *(__nv_bfloat162*)(sm + B_LO + off * 2) = Lo;
    }
    __syncthreads();

#pragma unroll
    for (int mi = 0; mi < 2; mi++)
#pragma unroll
        for (int ni = 0; ni < 8; ni++)
#pragma unroll
            for (int c = 0; c < 4; c++) acc[mi][ni][c] = 0.f;

    // ---- phase-2 mainloop: h @ W1 ----
#pragma unroll
    for (int term = 0; term < 3; term++) {
        const int abase = (term == 1) ? A_LO : A_HI;
        const int bbase = (term == 2) ? B_LO : B_HI;
#pragma unroll
        for (int k0 = 0; k0 < 128; k0 += 16) {
            uint32_t af[2][4];
#pragma unroll
            for (int mi = 0; mi < 2; mi++)
                ldm_x4(af[mi], smb + abase +
                       ((warpM * 32 + mi * 16 + lr) * STRD + k0 + lc) * 2);
            uint32_t bf[4][4];
#pragma unroll
            for (int q = 0; q < 4; q++)
                ldm_x4(bf[q], smb + bbase +
                       ((warpN * 64 + q * 16 + lr) * STRD + k0 + lc) * 2);
#pragma unroll
            for (int mi = 0; mi < 2; mi++)
#pragma unroll
                for (int q = 0; q < 4; q++) {
                    mma_bf16(acc[mi][2 * q],     af[mi], bf[q][0], bf[q][2]);
                    mma_bf16(acc[mi][2 * q + 1], af[mi], bf[q][1], bf[q][3]);
                }
        }
    }

    // ---- epilogue: g0 (fp32) + per-row dots with asrc/adst ----
    float sp[2][2], dp[2][2];
#pragma unroll
    for (int mi = 0; mi < 2; mi++) { sp[mi][0] = sp[mi][1] = 0.f; dp[mi][0] = dp[mi][1] = 0.f; }

    float2* C2 = (float2*)C;
#pragma unroll
    for (int mi = 0; mi < 2; mi++) {
        const int gr0 = row0 + warpM * 32 + mi * 16 + g;
        const int gr1 = gr0 + 8;
#pragma unroll
        for (int ni = 0; ni < 8; ni++) {
            const int col = warpN * 64 + ni * 8 + 2 * t4;
            float c0 = acc[mi][ni][0], c1 = acc[mi][ni][1];
            float c2 = acc[mi][ni][2], c3 = acc[mi][ni][3];
            sp[mi][0] = fmaf(c0, s_as[col], fmaf(c1, s_as[col + 1], sp[mi][0]));
            dp[mi][0] = fmaf(c0, s_ad[col], fmaf(c1, s_ad[col + 1], dp[mi][0]));
            sp[mi][1] = fmaf(c2, s_as[col], fmaf(c3, s_as[col + 1], sp[mi][1]));
            dp[mi][1] = fmaf(c2, s_ad[col], fmaf(c3, s_ad[col + 1], dp[mi][1]));
            if (gr0 < nrows) {
                float2 o; o.x = c0; o.y = c1;
                C2[gr0 * 64 + (col >> 1)] = o;
            }
            if (gr1 < nrows) {
                float2 o; o.x = c2; o.y = c3;
                C2[gr1 * 64 + (col >> 1)] = o;
            }
        }
    }
#pragma unroll
    for (int mi = 0; mi < 2; mi++)
#pragma unroll
        for (int hh = 0; hh < 2; hh++) {
#pragma unroll
            for (int o = 1; o <= 2; o <<= 1) {
                sp[mi][hh] += __shfl_xor_sync(0xffffffffu, sp[mi][hh], o);
                dp[mi][hh] += __shfl_xor_sync(0xffffffffu, dp[mi][hh], o);
            }
            if (t4 == 0) {
                int rl = warpM * 32 + mi * 16 + g + hh * 8;
                atomicAdd(&s_s[rl], sp[mi][hh]);
                atomicAdd(&s_d[rl], dp[mi][hh]);
            }
        }
    __syncthreads();
    if (tid < 128 && row0 + tid < nrows) {
        g_sv[row0 + tid] = s_s[tid];
        g_dv[row0 + tid] = s_d[tid];
    }
}

// ============ layer GEMM (layer 1): g = h @ W1; sv/dv dots ==================
// A comes pre-split from g_ahi/g_alo (written by agg0).
__global__ __launch_bounds__(256, 1) void gemm_lyr(
    const float* __restrict__ Bw,
    const float* __restrict__ asrc, const float* __restrict__ adst,
    float* __restrict__ C, int nrows)
{
    extern __shared__ __align__(16) char sm[];
    __shared__ float s_as[D], s_ad[D], s_s[D], s_d[D];
    const int tid  = threadIdx.x, wid = tid >> 5, lane = tid & 31;
    const int row0 = blockIdx.x * 128;
    const uint32_t smb = smem_u32(sm);
    const int A_HI = 0, A_LO = TILE_B, B_HI = 2 * TILE_B, B_LO = 3 * TILE_B;

    if (tid < 128) {
        s_as[tid] = asrc[tid];
        s_ad[tid] = adst[tid];
        s_s[tid] = 0.f;
        s_d[tid] = 0.f;
    }
    {
        const uint4* __restrict__ shi = (const uint4*)g_ahi + (size_t)row0 * 17;
        const uint4* __restrict__ slo = (const uint4*)g_alo + (size_t)row0 * 17;
        uint4* dhi = (uint4*)(sm + A_HI);
        uint4* dlo = (uint4*)(sm + A_LO);
#pragma unroll
        for (int i = 0; i < 9; i++) {
            int idx = tid + i * 256;
            if (idx < 128 * 17) { dhi[idx] = shi[idx]; dlo[idx] = slo[idx]; }
        }
    }
#pragma unroll
    for (int i = 0; i < 32; i++) {
        int idx = tid + i * 256;
        int n   = idx & 127;
        int kp  = idx >> 7;
        float b0 = Bw[(2 * kp) * 128 + n];
        float b1 = Bw[(2 * kp + 1) * 128 + n];
        __nv_bfloat162 Hi, Lo;
        split2(b0, b1, Hi, Lo);
        int off = n * STRD + 2 * kp;
        *(__nv_bfloat162*)(sm + B_HI + off * 2) = Hi;
        *(__nv_bfloat162*)(sm + B_LO + off * 2) = Lo;
    }
    __syncthreads();

    const int warpM = wid >> 1, warpN = wid & 1;
    const int lr = lane & 15, lc = (lane >> 4) * 8;

    float acc[2][8][4];
#pragma unroll
    for (int mi = 0; mi < 2; mi++)
#pragma unroll
        for (int ni = 0; ni < 8; ni++)
#pragma unroll
            for (int c = 0; c < 4; c++) acc[mi][ni][c] = 0.f;

#pragma unroll
    for (int term = 0; term < 3; term++) {
        const int abase = (term == 1) ? A_LO : A_HI;
        const int bbase = (term == 2) ? B_LO : B_HI;
#pragma unroll
        for (int k0 = 0; k0 < 128; k0 += 16) {
            uint32_t af[2][4];
#pragma unroll
            for (int mi = 0; mi < 2; mi++)
                ldm_x4(af[mi], smb + abase +
                       ((warpM * 32 + mi * 16 + lr) * STRD + k0 + lc) * 2);
            uint32_t bf[4][4];
#pragma unroll
            for (int q = 0; q < 4; q++)
                ldm_x4(bf[q], smb + bbase +
                       ((warpN * 64 + q * 16 + lr) * STRD + k0 + lc) * 2);
#pragma unroll
            for (int mi = 0; mi < 2; mi++)
#pragma unroll
                for (int q = 0; q < 4; q++) {
                    mma_bf16(acc[mi][2 * q],     af[mi], bf[q][0], bf[q][2]);
                    mma_bf16(acc[mi][2 * q + 1], af[mi], bf[q][1], bf[q][3]);
                }
        }
    }

    const int g = lane >> 2, t4 = lane & 3;
    float sp[2][2], dp[2][2];
#pragma unroll
    for (int mi = 0; mi < 2; mi++) { sp[mi][0] = sp[mi][1] = 0.f; dp[mi][0] = dp[mi][1] = 0.f; }

    float2* C2 = (float2*)C;
#pragma unroll
    for (int mi = 0; mi < 2; mi++) {
        const int gr0 = row0 + warpM * 32 + mi * 16 + g;
        const int gr1 = gr0 + 8;
#pragma unroll
        for (int ni = 0; ni < 8; ni++) {
            const int col = warpN * 64 + ni * 8 + 2 * t4;
            float c0 = acc[mi][ni][0], c1 = acc[mi][ni][1];
            float c2 = acc[mi][ni][2], c3 = acc[mi][ni][3];
            sp[mi][0] = fmaf(c0, s_as[col], fmaf(c1, s_as[col + 1], sp[mi][0]));
            dp[mi][0] = fmaf(c0, s_ad[col], fmaf(c1, s_ad[col + 1], dp[mi][0]));
            sp[mi][1] = fmaf(c2, s_as[col], fmaf(c3, s_as[col + 1], sp[mi][1]));
            dp[mi][1] = fmaf(c2, s_ad[col], fmaf(c3, s_ad[col + 1], dp[mi][1]));
            if (gr0 < nrows) {
                float2 o; o.x = c0; o.y = c1;
                C2[gr0 * 64 + (col >> 1)] = o;
            }
            if (gr1 < nrows) {
                float2 o; o.x = c2; o.y = c3;
                C2[gr1 * 64 + (col >> 1)] = o;
            }
        }
    }
#pragma unroll
    for (int mi = 0; mi < 2; mi++)
#pragma unroll
        for (int hh = 0; hh < 2; hh++) {
#pragma unroll
            for (int o = 1; o <= 2; o <<= 1) {
                sp[mi][hh] += __shfl_xor_sync(0xffffffffu, sp[mi][hh], o);
                dp[mi][hh] += __shfl_xor_sync(0xffffffffu, dp[mi][hh], o);
            }
            if (t4 == 0) {
                int rl = warpM * 32 + mi * 16 + g + hh * 8;
                atomicAdd(&s_s[rl], sp[mi][hh]);
                atomicAdd(&s_d[rl], dp[mi][hh]);
            }
        }
    __syncthreads();
    if (tid < 128 && row0 + tid < nrows) {
        g_sv[row0 + tid] = s_s[tid];
        g_dv[row0 + tid] = s_d[tid];
    }
}

// ---------------- CSR build (group edges by destination) -------------------
__global__ void k_deg_count(const int* __restrict__ dst) {
    int i = blockIdx.x * blockDim.x + threadIdx.x;
    if (i < NE) atomicAdd(&g_deg[dst[i]], 1);
}
__global__ void k_block_sums() {
    __shared__ int red[8];
    int b = blockIdx.x, t = threadIdx.x;
    int i = b * 256 + t;
    int v = (i < NN) ? (g_deg[i] + 1) : 0;           // +1 = self-loop
#pragma unroll
    for (int o = 16; o >= 1; o >>= 1) v += __shfl_xor_sync(0xffffffffu, v, o);
    if ((t & 31) == 0) red[t >> 5] = v;
    __syncthreads();
    if (t == 0) {
        int s = 0;
        for (int w = 0; w < 8; w++) s += red[w];
        g_bsum[b] = s;
    }
}
__global__ void k_scan_bsums() {                     // 1 block, 256 threads
    __shared__ int sh[256];
    int t = threadIdx.x;
    int v = (t < NBLK) ? g_bsum[t] : 0;
    sh[t] = v;
    __syncthreads();
    for (int o = 1; o < 256; o <<= 1) {
        int x = (t >= o) ? sh[t - o] : 0;
        __syncthreads();
        sh[t] += x;
        __syncthreads();
    }
    if (t < NBLK) g_bsum[t] = sh[t] - v;             // exclusive
    if (t == 255) g_off[NN] = sh[255];               // total = NE + NN
}
__global__ void k_scan_final() {
    __shared__ int sh[256];
    int b = blockIdx.x, t = threadIdx.x;
    int i = b * 256 + t;
    int v = (i < NN) ? (g_deg[i] + 1) : 0;           // +1 = self-loop
    sh[t] = v;
    __syncthreads();
    for (int o = 1; o < 256; o <<= 1) {
        int x = (t >= o) ? sh[t - o] : 0;
        __syncthreads();
        sh[t] += x;
        __syncthreads();
    }
    if (i < NN) {
        int p = g_bsum[b] + sh[t] - v;               // exclusive prefix
        g_off[i] = p;
        g_cur[i] = p;
        g_deg[i] = 0;                                // reset for next replay
    }
}
__global__ void k_scatter(const int* __restrict__ src, const int* __restrict__ dst) {
    int i = blockIdx.x * blockDim.x + threadIdx.x;
    if (i < NE) {
        int p = atomicAdd(&g_cur[dst[i]], 1);
        g_csr[p] = src[i];
    } else if (i < NE + NN) {
        int n = i - NE;
        int p = atomicAdd(&g_cur[n], 1);
        g_csr[p] = n;                                // self-loop edge
    }
}

// ---------------- per-dst softmax + aggregation ----------------------------
// warp-per-node: 32 lanes = 32 float4 = 128 feature dims; weights via shfl.
// If ahi != null: write result pre-split as bf16 hi/lo (layer-1 A).
// Else: write fp32 to outf (final output).
#define AGG_WPB 8
__global__ __launch_bounds__(256) void agg(const float* __restrict__ bias,
                                           float* __restrict__ outf,
                                           __nv_bfloat16* __restrict__ ahi,
                                           __nv_bfloat16* __restrict__ alo)
{
    const int wid = threadIdx.x >> 5, lane = threadIdx.x & 31;
    const int v = blockIdx.x * AGG_WPB + wid;
    if (v >= NN) return;
    const int beg = g_off[v], end = g_off[v + 1];
    const float dvv = g_dv[v];
    const float4* __restrict__ G4 = (const float4*)g_g;

    float4 acc = make_float4(0.f, 0.f, 0.f, 0.f);
    float z = 0.f;
    for (int cs = beg; cs < end; cs += 32) {
        const int cnt = min(32, end - cs);
        int u = 0; float wv = 0.f;
        if (lane < cnt) {
            u = g_csr[cs + lane];
            float e = g_sv[u] + dvv;
            e = (e > 0.f) ? e : 0.2f * e;
            wv = __expf(e);
            z += wv;
        }
        int e = 0;
        for (; e + 4 <= cnt; e += 4) {
            float w0 = __shfl_sync(0xffffffffu, wv, e);
            float w1 = __shfl_sync(0xffffffffu, wv, e + 1);
            float w2 = __shfl_sync(0xffffffffu, wv, e + 2);
            float w3 = __shfl_sync(0xffffffffu, wv, e + 3);
            int   u0 = __shfl_sync(0xffffffffu, u, e);
            int   u1 = __shfl_sync(0xffffffffu, u, e + 1);
            int   u2 = __shfl_sync(0xffffffffu, u, e + 2);
            int   u3 = __shfl_sync(0xffffffffu, u, e + 3);
            float4 g0 = G4[u0 * 32 + lane];
            float4 g1 = G4[u1 * 32 + lane];
            float4 g2 = G4[u2 * 32 + lane];
            float4 g3 = G4[u3 * 32 + lane];
            acc.x = fmaf(w0, g0.x, acc.x); acc.y = fmaf(w0, g0.y, acc.y);
            acc.z = fmaf(w0, g0.z, acc.z); acc.w = fmaf(w0, g0.w, acc.w);
            acc.x = fmaf(w1, g1.x, acc.x); acc.y = fmaf(w1, g1.y, acc.y);
            acc.z = fmaf(w1, g1.z, acc.z); acc.w = fmaf(w1, g1.w, acc.w);
            acc.x = fmaf(w2, g2.x, acc.x); acc.y = fmaf(w2, g2.y, acc.y);
            acc.z = fmaf(w2, g2.z, acc.z); acc.w = fmaf(w2, g2.w, acc.w);
            acc.x = fmaf(w3, g3.x, acc.x); acc.y = fmaf(w3, g3.y, acc.y);
            acc.z = fmaf(w3, g3.z, acc.z); acc.w = fmaf(w3, g3.w, acc.w);
        }
        for (; e < cnt; e++) {
            float we = __shfl_sync(0xffffffffu, wv, e);
            int   ue = __shfl_sync(0xffffffffu, u, e);
            float4 gv = G4[ue * 32 + lane];
            acc.x = fmaf(we, gv.x, acc.x); acc.y = fmaf(we, gv.y, acc.y);
            acc.z = fmaf(we, gv.z, acc.z); acc.w = fmaf(we, gv.w, acc.w);
        }
    }
#pragma unroll
    for (int o = 16; o >= 1; o >>= 1) z += __shfl_xor_sync(0xffffffffu, z, o);
    const float inv = 1.f / z;
    const float4 b4 = ((const float4*)bias)[lane];
    float4 o4;
    o4.x = acc.x * inv + b4.x;
    o4.y = acc.y * inv + b4.y;
    o4.z = acc.z * inv + b4.z;
    o4.w = acc.w * inv + b4.w;
    if (ahi) {
        __nv_bfloat162 h0, l0, h1, l1;
        split2(o4.x, o4.y, h0, l0);
        split2(o4.z, o4.w, h1, l1);
        __nv_bfloat162* ph = (__nv_bfloat162*)((char*)ahi + v * (STRD * 2));
        __nv_bfloat162* pl = (__nv_bfloat162*)((char*)alo + v * (STRD * 2));
        ph[2 * lane] = h0; ph[2 * lane + 1] = h1;
        pl[2 * lane] = l0; pl[2 * lane + 1] = l1;
    } else {
        ((float4*)outf)[v * 32 + lane] = o4;
    }
}

// ---------------- launch ---------------------------------------------------
// chain: fused(enc+lyr0) -> agg0 -> lyr1 -> agg1; CSR hidden on ONE extra
// stream (round-11 lesson: >1 extra stream leaks launch pools past teardown).
extern "C" void kernel_launch(void* const* d_in, const int* in_sizes, int n_in,
                              void* d_out, int out_size)
{
    (void)in_sizes; (void)n_in; (void)out_size;
    const float* x      = (const float*)d_in[0];
    const int*   ei     = (const int*)  d_in[1];
    const float* W_node = (const float*)d_in[3];
    const float* b_node = (const float*)d_in[4];
    // d_in[2,5,6,7,8] (edge_attr / W_edge / b_edge / lyr_We / lyr_be) are dead
    // code in the reference: their results are discarded before the output.
    const float* lyr_W  = (const float*)d_in[9];
    const float* att_s  = (const float*)d_in[10];
    const float* att_d  = (const float*)d_in[11];
    const float* lyr_b  = (const float*)d_in[12];
    float* out = (float*)d_out;

    float* pG;
    cudaGetSymbolAddress((void**)&pG, g_g);
    __nv_bfloat16 *pAhi, *pAlo;
    cudaGetSymbolAddress((void**)&pAhi, g_ahi);
    cudaGetSymbolAddress((void**)&pAlo, g_alo);

    const int SMEMSZ = 4 * TILE_B;                       // 139264 B
    cudaFuncSetAttribute(gemm_enc_lyr0,
                         cudaFuncAttributeMaxDynamicSharedMemorySize, SMEMSZ);
    cudaFuncSetAttribute(gemm_lyr,
                         cudaFuncAttributeMaxDynamicSharedMemorySize, SMEMSZ);

    const int* src = ei;
    const int* dst = ei + NE;
    const int AGG_F = (NN + AGG_WPB - 1) / AGG_WPB;

    cudaStream_t s2;
    cudaStreamCreateWithFlags(&s2, cudaStreamNonBlocking);
    cudaEvent_t evFork, evCsr;
    cudaEventCreateWithFlags(&evFork, cudaEventDisableTiming);
    cudaEventCreateWithFlags(&evCsr, cudaEventDisableTiming);

    cudaEventRecord(evFork, (cudaStream_t)0);
    cudaStreamWaitEvent(s2, evFork, 0);

    // s2: CSR build, fully hidden under the fused GEMM.
    k_deg_count<<<(NE + 255) / 256, 256, 0, s2>>>(dst);
    k_block_sums<<<NBLK, 256, 0, s2>>>();
    k_scan_bsums<<<1, 256, 0, s2>>>();
    k_scan_final<<<NBLK, 256, 0, s2>>>();
    k_scatter<<<(NE + NN + 255) / 256, 256, 0, s2>>>(src, dst);
    cudaEventRecord(evCsr, s2);

    // stream0: fused encoder + layer-0 GEMM (h never leaves the CTA)
    gemm_enc_lyr0<<<GB, 256, SMEMSZ>>>(x, W_node, b_node, lyr_W,
                                       att_s, att_d, pG, NN);

    // join CSR; agg layer 0 (writes split h for layer 1); lyr1; final agg.
    cudaStreamWaitEvent((cudaStream_t)0, evCsr, 0);
    agg<<<AGG_F, 256>>>(lyr_b, nullptr, pAhi, pAlo);
    gemm_lyr<<<GB, 256, SMEMSZ>>>(lyr_W + D * D, att_s + D, att_d + D, pG, NN);
    agg<<<AGG_F, 256>>>(lyr_b + D, out, nullptr, nullptr);
}